// round 6
// baseline (speedup 1.0000x reference)
#include <cuda_runtime.h>
#include <cstddef>

#define NUM_CLASSES 1000000
#define FEAT_DIM    128
#define BATCH       16384
#define ALPHA       0.5f

#define N_ELEMS   ((size_t)NUM_CLASSES * FEAT_DIM)   // 128,000,000
#define N_QUADS   (N_ELEMS / 4)                       // 32,000,000

// Scratch. .bss => zero-initialized at load. Each graph replay leaves these
// zeroed again (clean-on-exit in k_update), so no init kernel is needed.
__device__ float  g_sums[N_ELEMS];      // 512 MB static bss
__device__ float  g_counts[NUM_CLASSES];
__device__ int    g_owner[BATCH];       // 1 if batch elem is unique owner of its label
__device__ double g_loss;

// ---------------------------------------------------------------------------
// K1 (side stream, overlapped with the bulk copy): scatter features into
// per-class sums + counts, accumulate loss, elect one owner warp per label.
// One warp per batch element; lane k owns feature quad k.
// ---------------------------------------------------------------------------
__global__ void k_accum(const float* __restrict__ features,
                        const float* __restrict__ centers,
                        const int*   __restrict__ labels)
{
    const int gid  = blockIdx.x * blockDim.x + threadIdx.x;
    const int w    = gid >> 5;
    const int lane = gid & 31;
    if (w >= BATCH) return;

    const int l = labels[w];
    const float4 f = reinterpret_cast<const float4*>(features)[(size_t)w * 32 + lane];
    const float4 c = reinterpret_cast<const float4*>(centers )[(size_t)l * 32 + lane];

    float* srow = g_sums + (size_t)l * FEAT_DIM + lane * 4;
    atomicAdd(srow + 0, f.x);
    atomicAdd(srow + 1, f.y);
    atomicAdd(srow + 2, f.z);
    atomicAdd(srow + 3, f.w);
    if (lane == 0) {
        const float old = atomicAdd(&g_counts[l], 1.0f);
        g_owner[w] = (old == 0.0f) ? 1 : 0;   // unique owner of label l
    }

    const float dx = f.x - c.x, dy = f.y - c.y, dz = f.z - c.z, dw = f.w - c.w;
    float v = dx * dx + dy * dy + dz * dz + dw * dw;
    #pragma unroll
    for (int o = 16; o > 0; o >>= 1)
        v += __shfl_down_sync(0xffffffffu, v, o);
    if (lane == 0) atomicAdd(&g_loss, (double)v);
}

// ---------------------------------------------------------------------------
// K2: PURE bulk shifted copy  out[1 + i] = centers[i]  with dst-ALIGNED
// float4 stores, evict-first cache hints on both streams (each byte is
// touched exactly once; keep it out of L2's way). Thread j produces out quad
// j = {c[4j-1], c[4j..4j+2]}; the straddle element comes from the warp
// neighbor via shfl_up (lane 0 scalar-loads it). No sparse logic here.
// Thread 0 writes the head out[1..3] and the tail out[N].
// ---------------------------------------------------------------------------
__global__ void k_copy(const float* __restrict__ c, float* __restrict__ out)
{
    const size_t j = (size_t)blockIdx.x * blockDim.x + threadIdx.x;  // dst quad
    const float4 b = __ldcs(reinterpret_cast<const float4*>(c) + j);

    float pw = __shfl_up_sync(0xffffffffu, b.w, 1);
    if ((threadIdx.x & 31) == 0 && j > 0)
        pw = __ldg(c + 4 * j - 1);

    if (j == 0) {
        out[1] = b.x; out[2] = b.y; out[3] = b.z;
        out[N_ELEMS] = c[N_ELEMS - 1];               // tail element
    } else {
        __stcs(reinterpret_cast<float4*>(out) + j, make_float4(pw, b.x, b.y, b.z));
    }
}

// ---------------------------------------------------------------------------
// K3 (after join): owner warps overwrite their class row with the momentum
// update, then CLEAR the scratch they consumed (sums row, count, owner flag)
// so the next graph replay starts from zeroed state. Thread 0 emits the loss
// and zeroes the accumulator.
//   new_c = (1-ALPHA)*c + (ALPHA/cnt)*sum
// ---------------------------------------------------------------------------
__global__ void k_update(const float* __restrict__ centers,
                         const int*   __restrict__ labels,
                         float*       __restrict__ out)
{
    const int gid  = blockIdx.x * blockDim.x + threadIdx.x;
    const int w    = gid >> 5;
    const int lane = gid & 31;

    if (gid == 0) {
        out[0] = (float)(g_loss / (2.0 * (double)BATCH));
        g_loss = 0.0;
    }
    if (w >= BATCH) return;
    if (!g_owner[w]) return;                 // warp-uniform branch

    const int l = labels[w];
    const float cnt = g_counts[l];
    const float k1  = 1.0f - ALPHA;
    const float k2  = ALPHA / fmaxf(cnt, 1.0f);

    const size_t q = (size_t)l * 32 + lane;
    const float4 c = reinterpret_cast<const float4*>(centers)[q];
    const float4 s = reinterpret_cast<const float4*>(g_sums)[q];

    float* o = out + 1 + (size_t)l * FEAT_DIM + lane * 4;  // misaligned: scalar stores
    o[0] = k1 * c.x + k2 * s.x;
    o[1] = k1 * c.y + k2 * s.y;
    o[2] = k1 * c.z + k2 * s.z;
    o[3] = k1 * c.w + k2 * s.w;

    // clean-on-exit: restore zeroed scratch for the next replay
    reinterpret_cast<float4*>(g_sums)[q] = make_float4(0.f, 0.f, 0.f, 0.f);
    if (lane == 0) {
        g_counts[l] = 0.0f;
        g_owner[w]  = 0;
    }
}

// ---------------------------------------------------------------------------
// Capture-safe fork/join: k_accum runs on a side stream concurrently with the
// bulk copy on the main (capturing) stream; k_update runs after both. Stream
// and events are created/destroyed per call (no device-memory allocation, no
// cross-call state).
// ---------------------------------------------------------------------------
extern "C" void kernel_launch(void* const* d_in, const int* in_sizes, int n_in,
                              void* d_out, int out_size)
{
    const float* features = (const float*)d_in[0];
    const float* centers  = (const float*)d_in[1];
    const int*   labels   = (const int*)d_in[2];
    float*       out      = (float*)d_out;

    (void)in_sizes; (void)n_in; (void)out_size;

    const int warps_grid = (BATCH * 32) / 256;          // 2048 blocks of 256

    cudaStream_t s2;
    cudaEvent_t  eFork, eJoin;
    cudaStreamCreateWithFlags(&s2, cudaStreamNonBlocking);
    cudaEventCreateWithFlags(&eFork, cudaEventDisableTiming);
    cudaEventCreateWithFlags(&eJoin, cudaEventDisableTiming);

    // fork: side stream joins the capture graph via the event dependency
    cudaEventRecord(eFork, 0);
    cudaStreamWaitEvent(s2, eFork, 0);

    k_accum<<<warps_grid, 256, 0, s2>>>(features, centers, labels);     // side
    k_copy <<<(int)(N_QUADS / 256), 256>>>(centers, out);               // main

    // join: main stream waits for accum before the update
    cudaEventRecord(eJoin, s2);
    cudaStreamWaitEvent(0, eJoin, 0);

    k_update<<<warps_grid, 256>>>(centers, labels, out);

    cudaEventDestroy(eFork);
    cudaEventDestroy(eJoin);
    cudaStreamDestroy(s2);
}

// round 7
// speedup vs baseline: 1.0986x; 1.0986x over previous
#include <cuda_runtime.h>
#include <cstddef>

#define NUM_CLASSES 1000000
#define FEAT_DIM    128
#define BATCH       16384
#define ALPHA       0.5f

#define N_ELEMS   ((size_t)NUM_CLASSES * FEAT_DIM)   // 128,000,000
#define N_QUADS   (N_ELEMS / 4)                       // 32,000,000

// Scratch. .bss => zero-initialized at load. Each graph replay leaves these
// zeroed again (clean-on-exit in k_update), so no init kernel is needed.
__device__ float  g_sums[N_ELEMS];      // 512 MB static bss
__device__ float  g_counts[NUM_CLASSES];
__device__ int    g_owner[BATCH];       // 1 if batch elem is unique owner of its label
__device__ double g_loss;

// ---------------------------------------------------------------------------
// K1 (side stream, high priority): scatter features into per-class sums +
// counts, accumulate loss (BLOCK-level reduction -> 1 double atomic per block,
// 2048 total instead of 16384 single-address atomics), elect owner warps.
// One warp per batch element; lane k owns feature quad k.
// ---------------------------------------------------------------------------
__global__ void k_accum(const float* __restrict__ features,
                        const float* __restrict__ centers,
                        const int*   __restrict__ labels)
{
    const int gid  = blockIdx.x * blockDim.x + threadIdx.x;
    const int w    = gid >> 5;
    const int lane = gid & 31;
    const int wib  = threadIdx.x >> 5;          // warp-in-block (0..7)

    __shared__ float s_part[8];

    float v = 0.0f;
    if (w < BATCH) {
        const int l = labels[w];
        const float4 f = reinterpret_cast<const float4*>(features)[(size_t)w * 32 + lane];
        const float4 c = reinterpret_cast<const float4*>(centers )[(size_t)l * 32 + lane];

        float* srow = g_sums + (size_t)l * FEAT_DIM + lane * 4;
        atomicAdd(srow + 0, f.x);
        atomicAdd(srow + 1, f.y);
        atomicAdd(srow + 2, f.z);
        atomicAdd(srow + 3, f.w);
        if (lane == 0) {
            const float old = atomicAdd(&g_counts[l], 1.0f);
            g_owner[w] = (old == 0.0f) ? 1 : 0;   // unique owner of label l
        }

        const float dx = f.x - c.x, dy = f.y - c.y, dz = f.z - c.z, dw = f.w - c.w;
        v = dx * dx + dy * dy + dz * dz + dw * dw;
    }

    #pragma unroll
    for (int o = 16; o > 0; o >>= 1)
        v += __shfl_down_sync(0xffffffffu, v, o);
    if (lane == 0) s_part[wib] = v;
    __syncthreads();
    if (threadIdx.x == 0) {
        float tot = 0.0f;
        #pragma unroll
        for (int i = 0; i < 8; i++) tot += s_part[i];
        atomicAdd(&g_loss, (double)tot);
    }
}

// ---------------------------------------------------------------------------
// K2: PURE bulk shifted copy  out[1 + i] = centers[i]  with dst-ALIGNED
// float4 stores. Evict-first hints (__ldcs/__stcs) on the 1 GB stream serve
// two purposes: the stream itself is touch-once, AND marking its lines
// evict-first preserves the L2 residency of the scratch/center lines k_accum
// just touched, so k_update's scattered reads hit L2.
// Thread j produces out quad j = {c[4j-1], c[4j..4j+2]}; the straddle element
// comes from the warp neighbor via shfl_up (lane 0 scalar-loads it, L2-hot).
// Thread 0 writes the head out[1..3] and the tail out[N].
// ---------------------------------------------------------------------------
__global__ void k_copy(const float* __restrict__ c, float* __restrict__ out)
{
    const size_t j = (size_t)blockIdx.x * blockDim.x + threadIdx.x;  // dst quad
    const float4 b = __ldcs(reinterpret_cast<const float4*>(c) + j);

    float pw = __shfl_up_sync(0xffffffffu, b.w, 1);
    if ((threadIdx.x & 31) == 0 && j > 0)
        pw = __ldg(c + 4 * j - 1);

    if (j == 0) {
        out[1] = b.x; out[2] = b.y; out[3] = b.z;
        out[N_ELEMS] = c[N_ELEMS - 1];               // tail element
    } else {
        __stcs(reinterpret_cast<float4*>(out) + j, make_float4(pw, b.x, b.y, b.z));
    }
}

// ---------------------------------------------------------------------------
// K3 (after join): owner warps overwrite their class row with the momentum
// update (reads are L2-hot thanks to the evict-first copy), then CLEAR the
// scratch they consumed so the next graph replay starts from zeroed state.
// Thread 0 emits the loss and zeroes the accumulator.
//   new_c = (1-ALPHA)*c + (ALPHA/cnt)*sum
// ---------------------------------------------------------------------------
__global__ void k_update(const float* __restrict__ centers,
                         const int*   __restrict__ labels,
                         float*       __restrict__ out)
{
    const int gid  = blockIdx.x * blockDim.x + threadIdx.x;
    const int w    = gid >> 5;
    const int lane = gid & 31;

    if (gid == 0) {
        out[0] = (float)(g_loss / (2.0 * (double)BATCH));
        g_loss = 0.0;
    }
    if (w >= BATCH) return;
    if (!g_owner[w]) return;                 // warp-uniform branch

    const int l = labels[w];
    const float cnt = g_counts[l];
    const float k1  = 1.0f - ALPHA;
    const float k2  = ALPHA / fmaxf(cnt, 1.0f);

    const size_t q = (size_t)l * 32 + lane;
    const float4 c = reinterpret_cast<const float4*>(centers)[q];
    const float4 s = reinterpret_cast<const float4*>(g_sums)[q];

    float* o = out + 1 + (size_t)l * FEAT_DIM + lane * 4;  // misaligned: scalar stores
    o[0] = k1 * c.x + k2 * s.x;
    o[1] = k1 * c.y + k2 * s.y;
    o[2] = k1 * c.z + k2 * s.z;
    o[3] = k1 * c.w + k2 * s.w;

    // clean-on-exit: restore zeroed scratch for the next replay
    reinterpret_cast<float4*>(g_sums)[q] = make_float4(0.f, 0.f, 0.f, 0.f);
    if (lane == 0) {
        g_counts[l] = 0.0f;
        g_owner[w]  = 0;
    }
}

// ---------------------------------------------------------------------------
// Capture-safe fork/join: k_accum runs on a HIGH-PRIORITY side stream
// concurrently with the bulk copy on the main (capturing) stream; k_update
// runs after both. Stream/events created+destroyed per call (no device
// memory allocation, no cross-call state).
// ---------------------------------------------------------------------------
extern "C" void kernel_launch(void* const* d_in, const int* in_sizes, int n_in,
                              void* d_out, int out_size)
{
    const float* features = (const float*)d_in[0];
    const float* centers  = (const float*)d_in[1];
    const int*   labels   = (const int*)d_in[2];
    float*       out      = (float*)d_out;

    (void)in_sizes; (void)n_in; (void)out_size;

    const int warps_grid = (BATCH * 32) / 256;          // 2048 blocks of 256

    int prLo = 0, prHi = 0;
    cudaDeviceGetStreamPriorityRange(&prLo, &prHi);

    cudaStream_t s2;
    cudaEvent_t  eFork, eJoin;
    cudaStreamCreateWithPriority(&s2, cudaStreamNonBlocking, prHi);
    cudaEventCreateWithFlags(&eFork, cudaEventDisableTiming);
    cudaEventCreateWithFlags(&eJoin, cudaEventDisableTiming);

    // fork: side stream joins the capture graph via the event dependency
    cudaEventRecord(eFork, 0);
    cudaStreamWaitEvent(s2, eFork, 0);

    k_accum<<<warps_grid, 256, 0, s2>>>(features, centers, labels);     // side
    k_copy <<<(int)(N_QUADS / 256), 256>>>(centers, out);               // main

    // join: main stream waits for accum before the update
    cudaEventRecord(eJoin, s2);
    cudaStreamWaitEvent(0, eJoin, 0);

    k_update<<<warps_grid, 256>>>(centers, labels, out);

    cudaEventDestroy(eFork);
    cudaEventDestroy(eJoin);
    cudaStreamDestroy(s2);
}